// round 1
// baseline (speedup 1.0000x reference)
#include <cuda_runtime.h>

#define NB 32
#define NC 128
#define HW 4096
#define NROW (NB*NC)

// Scratch (device globals: allocation-free kernel_launch)
__device__ float g_A [NB*NC*HW];
__device__ float g_Bm[NB*NC*HW];
__device__ float g_V [NB*NC*HW];
__device__ float g_gdp[8*NB*NC*NC];
__device__ float g_gd [NB*NC*NC];
__device__ float g_mB[NROW], g_sB[NROW];   // sB = 1/(Z_B * HW)
__device__ float g_mV[NROW], g_sV[NROW];   // sV = 1/Z_V

// ---------------------------------------------------------------------------
// Kernel P: A/Bm/V projections.  out[o,n] = sum_c w[o,c]*x[c,n] + b[o]
// grid (HW/64, NB), 256 threads (16x16), microtile 8o x 4n, K=128 in 8 tiles of 16
// ---------------------------------------------------------------------------
__global__ __launch_bounds__(256) void proj_kernel(
    const float* __restrict__ x,
    const float* __restrict__ wA, const float* __restrict__ bA,
    const float* __restrict__ wB, const float* __restrict__ bB,
    const float* __restrict__ wV, const float* __restrict__ bV)
{
    __shared__ float sx[128][64];   // [c][n] 32 KB
    __shared__ float sw[128][17];   // [o][k] 8.5 KB, k-tile=16

    const int b  = blockIdx.y;
    const int n0 = blockIdx.x * 64;
    const int tid = threadIdx.x;
    const int tx = tid & 15, ty = tid >> 4;

    // load x tile (coalesced)
    {
        const int nl = tid & 63;
        const int c0 = tid >> 6;
        const float* xp = x + (size_t)b * NC * HW + n0 + nl;
        #pragma unroll 8
        for (int c = c0; c < 128; c += 4)
            sx[c][nl] = xp[(size_t)c * HW];
    }

    const float* ws[3] = {wA, wB, wV};
    const float* bs[3] = {bA, bB, bV};
    float* const outs[3] = {g_A, g_Bm, g_V};

    for (int m = 0; m < 3; m++) {
        float acc[8][4];
        #pragma unroll
        for (int a = 0; a < 8; a++)
            #pragma unroll
            for (int d = 0; d < 4; d++) acc[a][d] = 0.f;

        const float* wm = ws[m];
        for (int kt = 0; kt < 8; kt++) {
            __syncthreads();
            // load weight k-tile: sw[o][k] = w[o][kt*16+k]
            {
                const int k  = tid & 15;
                const int o0 = tid >> 4;
                #pragma unroll 8
                for (int o = o0; o < 128; o += 16)
                    sw[o][k] = wm[o * 128 + kt * 16 + k];
            }
            __syncthreads();
            #pragma unroll
            for (int k = 0; k < 16; k++) {
                float4 xv = *(const float4*)&sx[kt * 16 + k][tx * 4];
                #pragma unroll
                for (int a = 0; a < 8; a++) {
                    float wv = sw[ty * 8 + a][k];
                    acc[a][0] += wv * xv.x;
                    acc[a][1] += wv * xv.y;
                    acc[a][2] += wv * xv.z;
                    acc[a][3] += wv * xv.w;
                }
            }
        }

        float* op = outs[m] + (size_t)b * NC * HW + n0;
        #pragma unroll
        for (int a = 0; a < 8; a++) {
            const int o = ty * 8 + a;
            const float bias = bs[m][o];
            float4 v = make_float4(acc[a][0] + bias, acc[a][1] + bias,
                                   acc[a][2] + bias, acc[a][3] + bias);
            *(float4*)&op[(size_t)o * HW + tx * 4] = v;
        }
    }
}

// ---------------------------------------------------------------------------
// Kernel S: per-row softmax stats (max + 1/Z) for Bm (y=0) and V (y=1)
// grid (NROW, 2), 256 threads; each thread reads 16 elems
// ---------------------------------------------------------------------------
__global__ __launch_bounds__(256) void stats_kernel()
{
    const int row = blockIdx.x;
    const float* p = (blockIdx.y == 0 ? g_Bm : g_V) + (size_t)row * HW;
    const int tid = threadIdx.x;

    float v[16];
    float mx = -1e30f;
    #pragma unroll
    for (int i = 0; i < 16; i++) {
        v[i] = p[tid + i * 256];
        mx = fmaxf(mx, v[i]);
    }

    __shared__ float red[8];
    __shared__ float bmax;
    #pragma unroll
    for (int off = 16; off; off >>= 1)
        mx = fmaxf(mx, __shfl_xor_sync(0xffffffffu, mx, off));
    if ((tid & 31) == 0) red[tid >> 5] = mx;
    __syncthreads();
    if (tid == 0) {
        float m = red[0];
        #pragma unroll
        for (int i = 1; i < 8; i++) m = fmaxf(m, red[i]);
        bmax = m;
    }
    __syncthreads();
    const float m = bmax;

    float s = 0.f;
    #pragma unroll
    for (int i = 0; i < 16; i++) s += __expf(v[i] - m);
    #pragma unroll
    for (int off = 16; off; off >>= 1)
        s += __shfl_xor_sync(0xffffffffu, s, off);
    if ((tid & 31) == 0) red[tid >> 5] = s;
    __syncthreads();
    if (tid == 0) {
        float t = 0.f;
        #pragma unroll
        for (int i = 0; i < 8; i++) t += red[i];
        if (blockIdx.y == 0) { g_mB[row] = m; g_sB[row] = 1.0f / (t * (float)HW); }
        else                 { g_mV[row] = m; g_sV[row] = 1.0f / t; }
    }
}

// ---------------------------------------------------------------------------
// Kernel G: partial gd[s][b][i][j] = sum_{n in chunk s} exp(B[i,n]-mB[i]) * A[j,n]
// grid (8, NB), 256 threads (16x16), output tile 128x128, microtile 8i x 8j
// ---------------------------------------------------------------------------
__global__ __launch_bounds__(256) void gd_kernel()
{
    const int b = blockIdx.y, s = blockIdx.x;
    const int kbase = s * 512;
    const int tid = threadIdx.x;
    const int tx = tid & 15, ty = tid >> 4;

    __shared__ float sB[32][129];   // [k][i]
    __shared__ float sA[32][129];   // [k][j]

    float acc[8][8];
    #pragma unroll
    for (int a = 0; a < 8; a++)
        #pragma unroll
        for (int c = 0; c < 8; c++) acc[a][c] = 0.f;

    const float* Bp = g_Bm + (size_t)b * NC * HW;
    const float* Ap = g_A  + (size_t)b * NC * HW;
    const float* mB = g_mB + b * NC;

    for (int kt = 0; kt < 16; kt++) {
        __syncthreads();
        {
            const int k  = tid & 31;
            const int i0 = tid >> 5;
            const int kk = kbase + kt * 32 + k;
            #pragma unroll 4
            for (int i = i0; i < 128; i += 8) {
                sB[k][i] = __expf(Bp[(size_t)i * HW + kk] - mB[i]);
                sA[k][i] = Ap[(size_t)i * HW + kk];
            }
        }
        __syncthreads();
        #pragma unroll 4
        for (int k2 = 0; k2 < 32; k2++) {
            float bi[8], aj[8];
            #pragma unroll
            for (int a = 0; a < 8; a++) bi[a] = sB[k2][ty * 8 + a];
            #pragma unroll
            for (int c = 0; c < 8; c++) aj[c] = sA[k2][tx + 16 * c];
            #pragma unroll
            for (int a = 0; a < 8; a++)
                #pragma unroll
                for (int c = 0; c < 8; c++)
                    acc[a][c] += bi[a] * aj[c];
        }
    }

    float* gp = g_gdp + (((size_t)s * NB + b) * NC) * NC;
    #pragma unroll
    for (int a = 0; a < 8; a++) {
        const int i = ty * 8 + a;
        #pragma unroll
        for (int c = 0; c < 8; c++)
            gp[(size_t)i * NC + tx + 16 * c] = acc[a][c];
    }
}

// ---------------------------------------------------------------------------
// Kernel R: gd = (sum_s gdp[s]) * (1/(Z_B*HW)) per i-row
// ---------------------------------------------------------------------------
__global__ __launch_bounds__(256) void reduce_kernel()
{
    const int idx = blockIdx.x * 256 + threadIdx.x;   // < NB*NC*NC
    float sum = 0.f;
    #pragma unroll
    for (int s = 0; s < 8; s++)
        sum += g_gdp[(size_t)s * (NB * NC * NC) + idx];
    const int irow = idx >> 7;   // b*NC + i
    g_gd[idx] = sum * g_sB[irow];
}

// ---------------------------------------------------------------------------
// Kernel O: out[b,j,n] = sum_i softmaxV[i,n] * gd[i,j]
// grid (HW/64, NB), 256 threads (16x16), microtile 8j x 4n, K=128 in 4 tiles of 32
// ---------------------------------------------------------------------------
__global__ __launch_bounds__(256) void out_kernel(float* __restrict__ out)
{
    const int b  = blockIdx.y;
    const int n0 = blockIdx.x * 64;
    const int tid = threadIdx.x;
    const int tx = tid & 15, ty = tid >> 4;

    __shared__ float sg[32][129];   // [i][j]
    __shared__ float sv[32][64];    // [i][n]

    float acc[8][4];
    #pragma unroll
    for (int a = 0; a < 8; a++)
        #pragma unroll
        for (int d = 0; d < 4; d++) acc[a][d] = 0.f;

    const float* Vp = g_V  + (size_t)b * NC * HW;
    const float* gp = g_gd + (size_t)b * NC * NC;
    const float* mV = g_mV + b * NC;
    const float* sV = g_sV + b * NC;

    for (int kt = 0; kt < 4; kt++) {
        __syncthreads();
        {
            const int j  = tid & 127;
            const int i0 = tid >> 7;
            #pragma unroll 8
            for (int i = i0; i < 32; i += 2)
                sg[i][j] = gp[(size_t)(kt * 32 + i) * NC + j];
        }
        {
            const int n  = tid & 63;
            const int i0 = tid >> 6;
            #pragma unroll 4
            for (int i = i0; i < 32; i += 4) {
                const int row = kt * 32 + i;
                float v = Vp[(size_t)row * HW + n0 + n];
                sv[i][n] = __expf(v - mV[row]) * sV[row];
            }
        }
        __syncthreads();
        #pragma unroll 4
        for (int k = 0; k < 32; k++) {
            float4 vv = *(const float4*)&sv[k][tx * 4];
            #pragma unroll
            for (int a = 0; a < 8; a++) {
                float g = sg[k][ty * 8 + a];
                acc[a][0] += g * vv.x;
                acc[a][1] += g * vv.y;
                acc[a][2] += g * vv.z;
                acc[a][3] += g * vv.w;
            }
        }
    }

    float* op = out + (size_t)b * NC * HW + n0;
    #pragma unroll
    for (int a = 0; a < 8; a++) {
        const int j = ty * 8 + a;
        *(float4*)&op[(size_t)j * HW + tx * 4] =
            make_float4(acc[a][0], acc[a][1], acc[a][2], acc[a][3]);
    }
}

// ---------------------------------------------------------------------------
extern "C" void kernel_launch(void* const* d_in, const int* in_sizes, int n_in,
                              void* d_out, int out_size)
{
    const float* x  = (const float*)d_in[0];
    const float* wA = (const float*)d_in[1];
    const float* bA = (const float*)d_in[2];
    const float* wB = (const float*)d_in[3];
    const float* bB = (const float*)d_in[4];
    const float* wV = (const float*)d_in[5];
    const float* bV = (const float*)d_in[6];
    float* out = (float*)d_out;

    proj_kernel  <<<dim3(HW / 64, NB), 256>>>(x, wA, bA, wB, bB, wV, bV);
    stats_kernel <<<dim3(NROW, 2),     256>>>();
    gd_kernel    <<<dim3(8, NB),       256>>>();
    reduce_kernel<<<(NB * NC * NC) / 256, 256>>>();
    out_kernel   <<<dim3(HW / 64, NB), 256>>>(out);
}

// round 3
// speedup vs baseline: 1.3466x; 1.3466x over previous
#include <cuda_runtime.h>
#include <cuda_bf16.h>
#include <mma.h>
#include <cstdint>

using namespace nvcuda;

#define NB 32
#define NC 128
#define HW 4096
#define NROW (NB*NC)
#define KSPLIT 16

#define LDA 136   // padded ld for 128-wide bf16 tiles (272B rows, 17x16B -> conflict-free)
#define LDE 72    // padded ld for 64-wide bf16 tiles  (144B rows, 9x16B  -> conflict-free)

// Scratch (device globals: allocation-free kernel_launch)
__device__ float g_Bm[NB*NC*HW];
__device__ float g_V [NB*NC*HW];
__device__ __nv_bfloat16 g_Ah[NB*NC*HW];
__device__ __nv_bfloat16 g_Al[NB*NC*HW];
__device__ float g_gdp[KSPLIT*NB*NC*NC];
__device__ __nv_bfloat16 g_gTh[NB*NC*NC];   // gd^T [b][j][i] hi
__device__ __nv_bfloat16 g_gTl[NB*NC*NC];   // gd^T lo
__device__ float g_mB[NROW], g_sB[NROW];    // sB = 1/(Z_B*HW)
__device__ float g_mV[NROW], g_sV[NROW];    // sV = 1/Z_V
__device__ __nv_bfloat16 g_wh[3*NC*NC], g_wl[3*NC*NC];

__device__ __forceinline__ void split_bf16(float f, __nv_bfloat16& h, __nv_bfloat16& l) {
    h = __float2bfloat16(f);
    l = __float2bfloat16(f - __bfloat162float(h));
}

// ---------------------------------------------------------------------------
// Kernel W: weights -> bf16 hi/lo, plain [m][o][c]
// ---------------------------------------------------------------------------
__global__ __launch_bounds__(256) void wconv_kernel(
    const float* __restrict__ wA, const float* __restrict__ wB, const float* __restrict__ wV)
{
    const float* ws[3] = {wA, wB, wV};
    const int m = blockIdx.x;
    const float* w = ws[m];
    for (int idx = threadIdx.x; idx < NC*NC; idx += 256) {
        __nv_bfloat16 h, l;
        split_bf16(w[idx], h, l);
        g_wh[m*NC*NC + idx] = h;
        g_wl[m*NC*NC + idx] = l;
    }
}

// ---------------------------------------------------------------------------
// Kernel P: projections via wmma bf16 3-term split.
//   D_m[o,n] = sum_c w_m[o,c]*x[c,n]   (no bias: bB/bV softmax-invariant, bA folded later)
// grid (HW/128, NB), 256 threads (8 warps: 4 m-groups x 2 n-groups, each warp 2x4 tiles)
// smem: sXh|sXl|sWh|sWl [128][136] bf16 + stage [8][16][24] f32  (~151.5 KB)
// ---------------------------------------------------------------------------
#define PROJ_SMEM (4*128*LDA*2 + 8*16*24*4)

__global__ __launch_bounds__(256, 1) void proj_wmma(const float* __restrict__ x)
{
    extern __shared__ char smraw[];
    __nv_bfloat16* sXh = (__nv_bfloat16*)smraw;
    __nv_bfloat16* sXl = sXh + 128*LDA;
    __nv_bfloat16* sWh = sXl + 128*LDA;
    __nv_bfloat16* sWl = sWh + 128*LDA;
    float* stage = (float*)(sWl + 128*LDA);

    const int tid = threadIdx.x, w = tid >> 5, lane = tid & 31;
    const int b = blockIdx.y, n0 = blockIdx.x * 128;
    const int wm = w & 3, wn = w >> 2;

    // x tile -> bf16 hi/lo in smem [c][n]
    {
        const int c = tid >> 1, nh = (tid & 1) * 64;
        const float* xp = x + ((size_t)b * NC + c) * HW + n0 + nh;
        #pragma unroll 8
        for (int k = 0; k < 64; k += 2) {
            __nv_bfloat16 h0, l0, h1, l1;
            split_bf16(xp[k],   h0, l0);
            split_bf16(xp[k+1], h1, l1);
            *(__nv_bfloat162*)&sXh[c*LDA + nh + k] = __halves2bfloat162(h0, h1);
            *(__nv_bfloat162*)&sXl[c*LDA + nh + k] = __halves2bfloat162(l0, l1);
        }
    }

    for (int m = 0; m < 3; m++) {
        __syncthreads();
        // load weight matrix m into sW (64KB, from L2-resident image)
        {
            const int r = tid >> 1, half = (tid & 1) * 64;
            const uint4* sh = (const uint4*)(g_wh + m*NC*NC + r*NC + half);
            const uint4* sl = (const uint4*)(g_wl + m*NC*NC + r*NC + half);
            uint4* dh = (uint4*)&sWh[r*LDA + half];
            uint4* dl = (uint4*)&sWl[r*LDA + half];
            #pragma unroll
            for (int q = 0; q < 8; q++) { dh[q] = sh[q]; dl[q] = sl[q]; }
        }
        __syncthreads();

        wmma::fragment<wmma::accumulator, 16, 16, 16, float> acc[2][4];
        #pragma unroll
        for (int mt = 0; mt < 2; mt++)
            #pragma unroll
            for (int nt = 0; nt < 4; nt++)
                wmma::fill_fragment(acc[mt][nt], 0.0f);

        #pragma unroll
        for (int kt = 0; kt < 8; kt++) {
            wmma::fragment<wmma::matrix_a, 16, 16, 16, __nv_bfloat16, wmma::row_major> ah[2], al[2];
            #pragma unroll
            for (int mt = 0; mt < 2; mt++) {
                const int o0 = wm*32 + mt*16;
                wmma::load_matrix_sync(ah[mt], &sWh[o0*LDA + kt*16], LDA);
                wmma::load_matrix_sync(al[mt], &sWl[o0*LDA + kt*16], LDA);
            }
            #pragma unroll
            for (int nt = 0; nt < 4; nt++) {
                wmma::fragment<wmma::matrix_b, 16, 16, 16, __nv_bfloat16, wmma::row_major> bh, bl;
                const int c0 = wn*64 + nt*16;
                wmma::load_matrix_sync(bh, &sXh[kt*16*LDA + c0], LDA);
                wmma::load_matrix_sync(bl, &sXl[kt*16*LDA + c0], LDA);
                #pragma unroll
                for (int mt = 0; mt < 2; mt++) {
                    wmma::mma_sync(acc[mt][nt], ah[mt], bh, acc[mt][nt]);
                    wmma::mma_sync(acc[mt][nt], ah[mt], bl, acc[mt][nt]);
                    wmma::mma_sync(acc[mt][nt], al[mt], bh, acc[mt][nt]);
                }
            }
        }

        if (m == 0) {
            // A: stage, convert to bf16 hi/lo, store
            float* st = stage + w * 16 * 24;
            #pragma unroll
            for (int mt = 0; mt < 2; mt++)
                #pragma unroll
                for (int nt = 0; nt < 4; nt++) {
                    wmma::store_matrix_sync(st, acc[mt][nt], 24, wmma::mem_row_major);
                    __syncwarp();
                    const int r = lane & 15, c8 = (lane >> 4) * 8;
                    const int o = wm*32 + mt*16 + r;
                    const int nn = n0 + wn*64 + nt*16 + c8;
                    const float* sp = st + r*24 + c8;
                    const size_t gb = ((size_t)b * NC + o) * HW + nn;
                    #pragma unroll
                    for (int k = 0; k < 8; k += 2) {
                        __nv_bfloat16 h0, l0, h1, l1;
                        split_bf16(sp[k],   h0, l0);
                        split_bf16(sp[k+1], h1, l1);
                        *(__nv_bfloat162*)&g_Ah[gb + k] = __halves2bfloat162(h0, h1);
                        *(__nv_bfloat162*)&g_Al[gb + k] = __halves2bfloat162(l0, l1);
                    }
                    __syncwarp();
                }
        } else {
            float* dst = (m == 1) ? g_Bm : g_V;
            #pragma unroll
            for (int mt = 0; mt < 2; mt++)
                #pragma unroll
                for (int nt = 0; nt < 4; nt++) {
                    float* gp = dst + ((size_t)b * NC + wm*32 + mt*16) * HW + n0 + wn*64 + nt*16;
                    wmma::store_matrix_sync(gp, acc[mt][nt], HW, wmma::mem_row_major);
                }
        }
    }
}

// ---------------------------------------------------------------------------
// Kernel S: per-row softmax stats (max + 1/Z) for Bm (y=0) and V (y=1)
// ---------------------------------------------------------------------------
__global__ __launch_bounds__(256) void stats_kernel()
{
    const int row = blockIdx.x;
    const float* p = (blockIdx.y == 0 ? g_Bm : g_V) + (size_t)row * HW;
    const int tid = threadIdx.x;

    float v[16];
    float mx = -1e30f;
    #pragma unroll
    for (int i = 0; i < 16; i++) {
        v[i] = p[tid + i * 256];
        mx = fmaxf(mx, v[i]);
    }

    __shared__ float red[8];
    __shared__ float bmax;
    #pragma unroll
    for (int off = 16; off; off >>= 1)
        mx = fmaxf(mx, __shfl_xor_sync(0xffffffffu, mx, off));
    if ((tid & 31) == 0) red[tid >> 5] = mx;
    __syncthreads();
    if (tid == 0) {
        float m = red[0];
        #pragma unroll
        for (int i = 1; i < 8; i++) m = fmaxf(m, red[i]);
        bmax = m;
    }
    __syncthreads();
    const float m = bmax;

    float s = 0.f;
    #pragma unroll
    for (int i = 0; i < 16; i++) s += __expf(v[i] - m);
    #pragma unroll
    for (int off = 16; off; off >>= 1)
        s += __shfl_xor_sync(0xffffffffu, s, off);
    if ((tid & 31) == 0) red[tid >> 5] = s;
    __syncthreads();
    if (tid == 0) {
        float t = 0.f;
        #pragma unroll
        for (int i = 0; i < 8; i++) t += red[i];
        if (blockIdx.y == 0) { g_mB[row] = m; g_sB[row] = 1.0f / (t * (float)HW); }
        else                 { g_mV[row] = m; g_sV[row] = 1.0f / t; }
    }
}

// ---------------------------------------------------------------------------
// Kernel G: gdp[s][b][i][j] = sum_{n in 256-chunk} exp(Bm[i,n]-mB[i]) * A[j,n]
// wmma: A-op = E (row-major [i][n]), B-op = A (col-major view of [j][n])
// grid (KSPLIT, NB), 256 threads.
// smem: sEh|sEl|sAh|sAl [128][72] bf16 + mB[128] f32  (~74.2 KB)
// ---------------------------------------------------------------------------
#define GD_SMEM (4*128*LDE*2 + 512)

__global__ __launch_bounds__(256, 2) void gd_wmma()
{
    extern __shared__ char smraw[];
    __nv_bfloat16* sEh = (__nv_bfloat16*)smraw;
    __nv_bfloat16* sEl = sEh + 128*LDE;
    __nv_bfloat16* sAh = sEl + 128*LDE;
    __nv_bfloat16* sAl = sAh + 128*LDE;
    float* smB = (float*)(sAl + 128*LDE);

    const int tid = threadIdx.x, w = tid >> 5;
    const int b = blockIdx.y, kbase = blockIdx.x * 256;
    const int wm = w & 3, wn = w >> 2;

    if (tid < 128) smB[tid] = g_mB[b * NC + tid];

    wmma::fragment<wmma::accumulator, 16, 16, 16, float> acc[2][4];
    #pragma unroll
    for (int mt = 0; mt < 2; mt++)
        #pragma unroll
        for (int nt = 0; nt < 4; nt++)
            wmma::fill_fragment(acc[mt][nt], 0.0f);

    for (int kt4 = 0; kt4 < 4; kt4++) {
        __syncthreads();
        const int row = tid >> 1, ch = (tid & 1) * 32;
        const int kk0 = kbase + kt4 * 64 + ch;
        // E = exp(Bm - m) -> hi/lo
        {
            const float* Bp = g_Bm + ((size_t)b * NC + row) * HW + kk0;
            const float mb = smB[row];
            #pragma unroll 4
            for (int k = 0; k < 32; k += 2) {
                float e0 = __expf(Bp[k]   - mb);
                float e1 = __expf(Bp[k+1] - mb);
                __nv_bfloat16 h0, l0, h1, l1;
                split_bf16(e0, h0, l0);
                split_bf16(e1, h1, l1);
                *(__nv_bfloat162*)&sEh[row*LDE + ch + k] = __halves2bfloat162(h0, h1);
                *(__nv_bfloat162*)&sEl[row*LDE + ch + k] = __halves2bfloat162(l0, l1);
            }
        }
        // A tile copy (already bf16 pair in gmem)
        {
            const uint4* ah = (const uint4*)(g_Ah + ((size_t)b * NC + row) * HW + kk0);
            const uint4* al = (const uint4*)(g_Al + ((size_t)b * NC + row) * HW + kk0);
            uint4* dh = (uint4*)&sAh[row*LDE + ch];
            uint4* dl = (uint4*)&sAl[row*LDE + ch];
            #pragma unroll
            for (int q = 0; q < 4; q++) { dh[q] = ah[q]; dl[q] = al[q]; }
        }
        __syncthreads();

        #pragma unroll
        for (int kk = 0; kk < 4; kk++) {
            wmma::fragment<wmma::matrix_a, 16, 16, 16, __nv_bfloat16, wmma::row_major> ah[2], al[2];
            #pragma unroll
            for (int mt = 0; mt < 2; mt++) {
                const int i0 = wm*32 + mt*16;
                wmma::load_matrix_sync(ah[mt], &sEh[i0*LDE + kk*16], LDE);
                wmma::load_matrix_sync(al[mt], &sEl[i0*LDE + kk*16], LDE);
            }
            #pragma unroll
            for (int nt = 0; nt < 4; nt++) {
                wmma::fragment<wmma::matrix_b, 16, 16, 16, __nv_bfloat16, wmma::col_major> bh, bl;
                const int j0 = wn*64 + nt*16;
                wmma::load_matrix_sync(bh, &sAh[j0*LDE + kk*16], LDE);
                wmma::load_matrix_sync(bl, &sAl[j0*LDE + kk*16], LDE);
                #pragma unroll
                for (int mt = 0; mt < 2; mt++) {
                    wmma::mma_sync(acc[mt][nt], ah[mt], bh, acc[mt][nt]);
                    wmma::mma_sync(acc[mt][nt], ah[mt], bl, acc[mt][nt]);
                    wmma::mma_sync(acc[mt][nt], al[mt], bh, acc[mt][nt]);
                }
            }
        }
    }

    float* gp = g_gdp + ((size_t)blockIdx.x * NB + b) * NC * NC;
    #pragma unroll
    for (int mt = 0; mt < 2; mt++)
        #pragma unroll
        for (int nt = 0; nt < 4; nt++)
            wmma::store_matrix_sync(gp + (wm*32 + mt*16) * NC + wn*64 + nt*16,
                                    acc[mt][nt], NC, wmma::mem_row_major);
}

// ---------------------------------------------------------------------------
// Kernel R: gd = (sum_s gdp)*sB[i] + bA[j]/HW; write transposed bf16 hi/lo gT[b][j][i]
// ---------------------------------------------------------------------------
__global__ __launch_bounds__(256) void reduce_kernel(const float* __restrict__ bA)
{
    const int idx = blockIdx.x * 256 + threadIdx.x;   // b*16384 + i*128 + j
    const int bq = idx >> 14, i = (idx >> 7) & 127, j = idx & 127;
    float sum = 0.f;
    #pragma unroll
    for (int s = 0; s < KSPLIT; s++)
        sum += g_gdp[(size_t)s * (NB*NC*NC) + idx];
    const float val = sum * g_sB[bq * NC + i] + bA[j] * (1.0f / (float)HW);
    __nv_bfloat16 h, l;
    split_bf16(val, h, l);
    const size_t t = (size_t)bq * NC * NC + (size_t)j * NC + i;
    g_gTh[t] = h;
    g_gTl[t] = l;
}

// ---------------------------------------------------------------------------
// Kernel O: out[b,j,n] = sum_i av[i,n]*gd[i,j];  av = exp(V-mV)*sV
// wmma: A-op = gd^T (row-major [j][i]), B-op = av (row-major [i][n]), K=128
// grid (HW/128, NB), 256 threads. smem: sGh|sGl|sFh|sFl [128][136]  (~136 KB)
// ---------------------------------------------------------------------------
#define OUT_SMEM (4*128*LDA*2)

__global__ __launch_bounds__(256, 1) void out_wmma(float* __restrict__ out)
{
    extern __shared__ char smraw[];
    __nv_bfloat16* sGh = (__nv_bfloat16*)smraw;
    __nv_bfloat16* sGl = sGh + 128*LDA;
    __nv_bfloat16* sFh = sGl + 128*LDA;
    __nv_bfloat16* sFl = sFh + 128*LDA;

    const int tid = threadIdx.x, w = tid >> 5;
    const int b = blockIdx.y, n0 = blockIdx.x * 128;
    const int wm = w & 3, wn = w >> 2;

    // gd^T tiles (bf16 pair, whole [128][128])
    {
        const int j = tid >> 1, ih = (tid & 1) * 64;
        const uint4* gh = (const uint4*)(g_gTh + (size_t)b * NC * NC + j * NC + ih);
        const uint4* gl = (const uint4*)(g_gTl + (size_t)b * NC * NC + j * NC + ih);
        uint4* dh = (uint4*)&sGh[j*LDA + ih];
        uint4* dl = (uint4*)&sGl[j*LDA + ih];
        #pragma unroll
        for (int q = 0; q < 8; q++) { dh[q] = gh[q]; dl[q] = gl[q]; }
    }
    // av tile: exp(V - mV)*sV -> bf16 pair
    {
        const int i = tid >> 1, nh = (tid & 1) * 64;
        const float* Vp = g_V + ((size_t)b * NC + i) * HW + n0 + nh;
        const float mv = g_mV[b * NC + i], sv = g_sV[b * NC + i];
        #pragma unroll 8
        for (int k = 0; k < 64; k += 2) {
            float f0 = __expf(Vp[k]   - mv) * sv;
            float f1 = __expf(Vp[k+1] - mv) * sv;
            __nv_bfloat16 h0, l0, h1, l1;
            split_bf16(f0, h0, l0);
            split_bf16(f1, h1, l1);
            *(__nv_bfloat162*)&sFh[i*LDA + nh + k] = __halves2bfloat162(h0, h1);
            *(__nv_bfloat162*)&sFl[i*LDA + nh + k] = __halves2bfloat162(l0, l1);
        }
    }
    __syncthreads();

    wmma::fragment<wmma::accumulator, 16, 16, 16, float> acc[2][4];
    #pragma unroll
    for (int mt = 0; mt < 2; mt++)
        #pragma unroll
        for (int nt = 0; nt < 4; nt++)
            wmma::fill_fragment(acc[mt][nt], 0.0f);

    #pragma unroll
    for (int kt = 0; kt < 8; kt++) {
        wmma::fragment<wmma::matrix_a, 16, 16, 16, __nv_bfloat16, wmma::row_major> ah[2], al[2];
        #pragma unroll
        for (int mt = 0; mt < 2; mt++) {
            const int j0 = wm*32 + mt*16;
            wmma::load_matrix_sync(ah[mt], &sGh[j0*LDA + kt*16], LDA);
            wmma::load_matrix_sync(al[mt], &sGl[j0*LDA + kt*16], LDA);
        }
        #pragma unroll
        for (int nt = 0; nt < 4; nt++) {
            wmma::fragment<wmma::matrix_b, 16, 16, 16, __nv_bfloat16, wmma::row_major> bh, bl;
            const int c0 = wn*64 + nt*16;
            wmma::load_matrix_sync(bh, &sFh[kt*16*LDA + c0], LDA);
            wmma::load_matrix_sync(bl, &sFl[kt*16*LDA + c0], LDA);
            #pragma unroll
            for (int mt = 0; mt < 2; mt++) {
                wmma::mma_sync(acc[mt][nt], ah[mt], bh, acc[mt][nt]);
                wmma::mma_sync(acc[mt][nt], ah[mt], bl, acc[mt][nt]);
                wmma::mma_sync(acc[mt][nt], al[mt], bh, acc[mt][nt]);
            }
        }
    }

    #pragma unroll
    for (int mt = 0; mt < 2; mt++)
        #pragma unroll
        for (int nt = 0; nt < 4; nt++) {
            float* gp = out + ((size_t)b * NC + wm*32 + mt*16) * HW + n0 + wn*64 + nt*16;
            wmma::store_matrix_sync(gp, acc[mt][nt], HW, wmma::mem_row_major);
        }
}

// ---------------------------------------------------------------------------
extern "C" void kernel_launch(void* const* d_in, const int* in_sizes, int n_in,
                              void* d_out, int out_size)
{
    const float* x  = (const float*)d_in[0];
    const float* wA = (const float*)d_in[1];
    const float* bA = (const float*)d_in[2];
    const float* wB = (const float*)d_in[3];
    const float* bB = (const float*)d_in[4];  // unused: softmax shift-invariant
    const float* wV = (const float*)d_in[5];
    const float* bV = (const float*)d_in[6];  // unused: softmax shift-invariant
    (void)bB; (void)bV;
    float* out = (float*)d_out;

    cudaFuncSetAttribute(proj_wmma, cudaFuncAttributeMaxDynamicSharedMemorySize, PROJ_SMEM);
    cudaFuncSetAttribute(gd_wmma,   cudaFuncAttributeMaxDynamicSharedMemorySize, GD_SMEM);
    cudaFuncSetAttribute(out_wmma,  cudaFuncAttributeMaxDynamicSharedMemorySize, OUT_SMEM);

    wconv_kernel <<<3, 256>>>(wA, wB, wV);
    proj_wmma    <<<dim3(HW/128, NB), 256, PROJ_SMEM>>>(x);
    stats_kernel <<<dim3(NROW, 2), 256>>>();
    gd_wmma      <<<dim3(KSPLIT, NB), 256, GD_SMEM>>>();
    reduce_kernel<<<(NB*NC*NC)/256, 256>>>(bA);
    out_wmma     <<<dim3(HW/128, NB), 256, OUT_SMEM>>>(out);
}

// round 4
// speedup vs baseline: 1.5427x; 1.1456x over previous
#include <cuda_runtime.h>
#include <cuda_bf16.h>
#include <mma.h>
#include <cstdint>

using namespace nvcuda;

#define NB 32
#define NC 128
#define HW 4096
#define NROW (NB*NC)
#define KSPLIT 16

#define LDA 136   // padded ld for 128-wide bf16 tiles (272B rows -> conflict-free)
#define LDE 72    // padded ld for 64-wide bf16 tiles
#define LDW 24    // padded ld for 16-wide bf16 k-chunks (48B rows -> conflict-free)

// Scratch (device globals: allocation-free kernel_launch)
__device__ float g_Bm[NB*NC*HW];
__device__ float g_V [NB*NC*HW];
__device__ __nv_bfloat16 g_Ah[NB*NC*HW];
__device__ __nv_bfloat16 g_Al[NB*NC*HW];
__device__ float g_gdp[KSPLIT*NB*NC*NC];
__device__ __nv_bfloat16 g_gTh[NB*NC*NC];   // gd^T [b][j][i] hi
__device__ __nv_bfloat16 g_gTl[NB*NC*NC];   // gd^T lo
__device__ float g_mB[NROW], g_sB[NROW];    // sB = 1/(Z_B*HW)
__device__ float g_mV[NROW], g_sV[NROW];    // sV = 1/Z_V
__device__ __nv_bfloat16 g_wh[3*NC*NC], g_wl[3*NC*NC];

__device__ __forceinline__ void split_bf16(float f, __nv_bfloat16& h, __nv_bfloat16& l) {
    h = __float2bfloat16(f);
    l = __float2bfloat16(f - __bfloat162float(h));
}

// ---------------------------------------------------------------------------
// Kernel W: weights -> bf16 hi/lo, plain [m][o][c]
// ---------------------------------------------------------------------------
__global__ __launch_bounds__(256) void wconv_kernel(
    const float* __restrict__ wA, const float* __restrict__ wB, const float* __restrict__ wV)
{
    const float* ws[3] = {wA, wB, wV};
    const int m = blockIdx.x;
    const float* w = ws[m];
    for (int idx = threadIdx.x; idx < NC*NC; idx += 256) {
        __nv_bfloat16 h, l;
        split_bf16(w[idx], h, l);
        g_wh[m*NC*NC + idx] = h;
        g_wl[m*NC*NC + idx] = l;
    }
}

// ---------------------------------------------------------------------------
// Kernel P: projections via wmma bf16 3-term split, k-chunked double-buffered W.
//   D_m[o,n] = sum_c w_m[o,c]*x[c,n]  (bB/bV softmax-invariant, bA folded later)
// grid (HW/128, NB), 256 threads (8 warps: 4 o-groups x 2 n-groups, warp 2x4 tiles)
// smem: sXh|sXl [128][136] + W 2buf x (h+l)[128][24] + stage 8x16x20 f32  (~102 KB)
// ---------------------------------------------------------------------------
#define PROJ_SMEM (2*128*LDA*2 + 2*2*128*LDW*2 + 8*16*20*4)

__global__ __launch_bounds__(256, 2) void proj_wmma(const float* __restrict__ x)
{
    extern __shared__ char smraw[];
    __nv_bfloat16* sXh = (__nv_bfloat16*)smraw;
    __nv_bfloat16* sXl = sXh + 128*LDA;
    __nv_bfloat16* sW  = sXl + 128*LDA;               // 2 bufs, each (h:128*LDW | l:128*LDW)
    float* stage = (float*)(sW + 4*128*LDW);

    const int tid = threadIdx.x, w = tid >> 5, lane = tid & 31;
    const int b = blockIdx.y, n0 = blockIdx.x * 128;
    const int wm = w & 3, wn = w >> 2;
    const int o_ = tid >> 1, k8_ = (tid & 1) * 8;

    // x tile -> bf16 hi/lo in smem [c][n]
    {
        const int c = tid >> 1, nh = (tid & 1) * 64;
        const float* xp = x + ((size_t)b * NC + c) * HW + n0 + nh;
        #pragma unroll 8
        for (int k = 0; k < 64; k += 2) {
            __nv_bfloat16 h0, l0, h1, l1;
            split_bf16(xp[k],   h0, l0);
            split_bf16(xp[k+1], h1, l1);
            *(__nv_bfloat162*)&sXh[c*LDA + nh + k] = __halves2bfloat162(h0, h1);
            *(__nv_bfloat162*)&sXl[c*LDA + nh + k] = __halves2bfloat162(l0, l1);
        }
    }

    for (int m = 0; m < 3; m++) {
        const __nv_bfloat16* wh = g_wh + m*NC*NC + o_*NC + k8_;
        const __nv_bfloat16* wl = g_wl + m*NC*NC + o_*NC + k8_;

        // chunk 0 -> buf 0
        {
            uint4 h = *(const uint4*)wh;
            uint4 l = *(const uint4*)wl;
            __syncthreads();   // protect buf0 (read last at kt=6 of prev m) + x tile (m=0)
            *(uint4*)&sW[0*2*128*LDW + o_*LDW + k8_]           = h;
            *(uint4*)&sW[0*2*128*LDW + 128*LDW + o_*LDW + k8_] = l;
        }
        __syncthreads();

        wmma::fragment<wmma::accumulator, 16, 16, 16, float> acc[2][4];
        #pragma unroll
        for (int mt = 0; mt < 2; mt++)
            #pragma unroll
            for (int nt = 0; nt < 4; nt++)
                wmma::fill_fragment(acc[mt][nt], 0.0f);

        #pragma unroll
        for (int kt = 0; kt < 8; kt++) {
            const int cur = kt & 1;
            __nv_bfloat16* bWh = sW + cur*2*128*LDW;
            __nv_bfloat16* bWl = bWh + 128*LDW;

            uint4 ph, pl;
            if (kt < 7) {
                ph = *(const uint4*)(wh + (kt+1)*16);
                pl = *(const uint4*)(wl + (kt+1)*16);
            }

            wmma::fragment<wmma::matrix_a, 16, 16, 16, __nv_bfloat16, wmma::row_major> ah[2], al[2];
            #pragma unroll
            for (int mt = 0; mt < 2; mt++) {
                const int o0 = wm*32 + mt*16;
                wmma::load_matrix_sync(ah[mt], &bWh[o0*LDW], LDW);
                wmma::load_matrix_sync(al[mt], &bWl[o0*LDW], LDW);
            }
            #pragma unroll
            for (int nt = 0; nt < 4; nt++) {
                wmma::fragment<wmma::matrix_b, 16, 16, 16, __nv_bfloat16, wmma::row_major> bh, bl;
                const int c0 = wn*64 + nt*16;
                wmma::load_matrix_sync(bh, &sXh[kt*16*LDA + c0], LDA);
                wmma::load_matrix_sync(bl, &sXl[kt*16*LDA + c0], LDA);
                #pragma unroll
                for (int mt = 0; mt < 2; mt++) {
                    wmma::mma_sync(acc[mt][nt], ah[mt], bh, acc[mt][nt]);
                    wmma::mma_sync(acc[mt][nt], ah[mt], bl, acc[mt][nt]);
                    wmma::mma_sync(acc[mt][nt], al[mt], bh, acc[mt][nt]);
                }
            }

            if (kt < 7) {
                __nv_bfloat16* nWh = sW + (cur^1)*2*128*LDW;
                *(uint4*)&nWh[o_*LDW + k8_]           = ph;
                *(uint4*)&nWh[128*LDW + o_*LDW + k8_] = pl;
            }
            __syncthreads();
        }

        if (m == 0) {
            // A: stage, convert to bf16 hi/lo, store
            float* st = stage + w * 16 * 20;
            #pragma unroll
            for (int mt = 0; mt < 2; mt++)
                #pragma unroll
                for (int nt = 0; nt < 4; nt++) {
                    wmma::store_matrix_sync(st, acc[mt][nt], 20, wmma::mem_row_major);
                    __syncwarp();
                    const int r = lane & 15, c8 = (lane >> 4) * 8;
                    const int o = wm*32 + mt*16 + r;
                    const int nn = n0 + wn*64 + nt*16 + c8;
                    const float* sp = st + r*20 + c8;
                    const size_t gb = ((size_t)b * NC + o) * HW + nn;
                    #pragma unroll
                    for (int k = 0; k < 8; k += 2) {
                        __nv_bfloat16 h0, l0, h1, l1;
                        split_bf16(sp[k],   h0, l0);
                        split_bf16(sp[k+1], h1, l1);
                        *(__nv_bfloat162*)&g_Ah[gb + k] = __halves2bfloat162(h0, h1);
                        *(__nv_bfloat162*)&g_Al[gb + k] = __halves2bfloat162(l0, l1);
                    }
                    __syncwarp();
                }
        } else {
            float* dst = (m == 1) ? g_Bm : g_V;
            #pragma unroll
            for (int mt = 0; mt < 2; mt++)
                #pragma unroll
                for (int nt = 0; nt < 4; nt++) {
                    float* gp = dst + ((size_t)b * NC + wm*32 + mt*16) * HW + n0 + wn*64 + nt*16;
                    wmma::store_matrix_sync(gp, acc[mt][nt], HW, wmma::mem_row_major);
                }
        }
    }
}

// ---------------------------------------------------------------------------
// Kernel S: per-row softmax stats (max + 1/Z) for Bm (y=0) and V (y=1)
// ---------------------------------------------------------------------------
__global__ __launch_bounds__(256) void stats_kernel()
{
    const int row = blockIdx.x;
    const float* p = (blockIdx.y == 0 ? g_Bm : g_V) + (size_t)row * HW;
    const int tid = threadIdx.x;

    float v[16];
    float mx = -1e30f;
    #pragma unroll
    for (int i = 0; i < 16; i++) {
        v[i] = p[tid + i * 256];
        mx = fmaxf(mx, v[i]);
    }

    __shared__ float red[8];
    __shared__ float bmax;
    #pragma unroll
    for (int off = 16; off; off >>= 1)
        mx = fmaxf(mx, __shfl_xor_sync(0xffffffffu, mx, off));
    if ((tid & 31) == 0) red[tid >> 5] = mx;
    __syncthreads();
    if (tid == 0) {
        float m = red[0];
        #pragma unroll
        for (int i = 1; i < 8; i++) m = fmaxf(m, red[i]);
        bmax = m;
    }
    __syncthreads();
    const float m = bmax;

    float s = 0.f;
    #pragma unroll
    for (int i = 0; i < 16; i++) s += __expf(v[i] - m);
    #pragma unroll
    for (int off = 16; off; off >>= 1)
        s += __shfl_xor_sync(0xffffffffu, s, off);
    if ((tid & 31) == 0) red[tid >> 5] = s;
    __syncthreads();
    if (tid == 0) {
        float t = 0.f;
        #pragma unroll
        for (int i = 0; i < 8; i++) t += red[i];
        if (blockIdx.y == 0) { g_mB[row] = m; g_sB[row] = 1.0f / (t * (float)HW); }
        else                 { g_mV[row] = m; g_sV[row] = 1.0f / t; }
    }
}

// ---------------------------------------------------------------------------
// Kernel G: gdp[s][b][i][j] = sum_{n in 256-chunk} exp(Bm[i,n]-mB[i]) * A[j,n]
// (unchanged from R3 — measured 119us, L1-bound)
// ---------------------------------------------------------------------------
#define GD_SMEM (4*128*LDE*2 + 512)

__global__ __launch_bounds__(256, 2) void gd_wmma()
{
    extern __shared__ char smraw[];
    __nv_bfloat16* sEh = (__nv_bfloat16*)smraw;
    __nv_bfloat16* sEl = sEh + 128*LDE;
    __nv_bfloat16* sAh = sEl + 128*LDE;
    __nv_bfloat16* sAl = sAh + 128*LDE;
    float* smB = (float*)(sAl + 128*LDE);

    const int tid = threadIdx.x, w = tid >> 5;
    const int b = blockIdx.y, kbase = blockIdx.x * 256;
    const int wm = w & 3, wn = w >> 2;

    if (tid < 128) smB[tid] = g_mB[b * NC + tid];

    wmma::fragment<wmma::accumulator, 16, 16, 16, float> acc[2][4];
    #pragma unroll
    for (int mt = 0; mt < 2; mt++)
        #pragma unroll
        for (int nt = 0; nt < 4; nt++)
            wmma::fill_fragment(acc[mt][nt], 0.0f);

    for (int kt4 = 0; kt4 < 4; kt4++) {
        __syncthreads();
        const int row = tid >> 1, ch = (tid & 1) * 32;
        const int kk0 = kbase + kt4 * 64 + ch;
        {
            const float* Bp = g_Bm + ((size_t)b * NC + row) * HW + kk0;
            const float mb = smB[row];
            #pragma unroll 4
            for (int k = 0; k < 32; k += 2) {
                float e0 = __expf(Bp[k]   - mb);
                float e1 = __expf(Bp[k+1] - mb);
                __nv_bfloat16 h0, l0, h1, l1;
                split_bf16(e0, h0, l0);
                split_bf16(e1, h1, l1);
                *(__nv_bfloat162*)&sEh[row*LDE + ch + k] = __halves2bfloat162(h0, h1);
                *(__nv_bfloat162*)&sEl[row*LDE + ch + k] = __halves2bfloat162(l0, l1);
            }
        }
        {
            const uint4* ah = (const uint4*)(g_Ah + ((size_t)b * NC + row) * HW + kk0);
            const uint4* al = (const uint4*)(g_Al + ((size_t)b * NC + row) * HW + kk0);
            uint4* dh = (uint4*)&sAh[row*LDE + ch];
            uint4* dl = (uint4*)&sAl[row*LDE + ch];
            #pragma unroll
            for (int q = 0; q < 4; q++) { dh[q] = ah[q]; dl[q] = al[q]; }
        }
        __syncthreads();

        #pragma unroll
        for (int kk = 0; kk < 4; kk++) {
            wmma::fragment<wmma::matrix_a, 16, 16, 16, __nv_bfloat16, wmma::row_major> ah[2], al[2];
            #pragma unroll
            for (int mt = 0; mt < 2; mt++) {
                const int i0 = wm*32 + mt*16;
                wmma::load_matrix_sync(ah[mt], &sEh[i0*LDE + kk*16], LDE);
                wmma::load_matrix_sync(al[mt], &sEl[i0*LDE + kk*16], LDE);
            }
            #pragma unroll
            for (int nt = 0; nt < 4; nt++) {
                wmma::fragment<wmma::matrix_b, 16, 16, 16, __nv_bfloat16, wmma::col_major> bh, bl;
                const int j0 = wn*64 + nt*16;
                wmma::load_matrix_sync(bh, &sAh[j0*LDE + kk*16], LDE);
                wmma::load_matrix_sync(bl, &sAl[j0*LDE + kk*16], LDE);
                #pragma unroll
                for (int mt = 0; mt < 2; mt++) {
                    wmma::mma_sync(acc[mt][nt], ah[mt], bh, acc[mt][nt]);
                    wmma::mma_sync(acc[mt][nt], ah[mt], bl, acc[mt][nt]);
                    wmma::mma_sync(acc[mt][nt], al[mt], bh, acc[mt][nt]);
                }
            }
        }
    }

    float* gp = g_gdp + ((size_t)blockIdx.x * NB + b) * NC * NC;
    #pragma unroll
    for (int mt = 0; mt < 2; mt++)
        #pragma unroll
        for (int nt = 0; nt < 4; nt++)
            wmma::store_matrix_sync(gp + (wm*32 + mt*16) * NC + wn*64 + nt*16,
                                    acc[mt][nt], NC, wmma::mem_row_major);
}

// ---------------------------------------------------------------------------
// Kernel R: gd = (sum_s gdp)*sB[i] + bA[j]/HW; write transposed bf16 hi/lo gT[b][j][i]
// ---------------------------------------------------------------------------
__global__ __launch_bounds__(256) void reduce_kernel(const float* __restrict__ bA)
{
    const int idx = blockIdx.x * 256 + threadIdx.x;   // b*16384 + i*128 + j
    const int bq = idx >> 14, i = (idx >> 7) & 127, j = idx & 127;
    float sum = 0.f;
    #pragma unroll
    for (int s = 0; s < KSPLIT; s++)
        sum += g_gdp[(size_t)s * (NB*NC*NC) + idx];
    const float val = sum * g_sB[bq * NC + i] + bA[j] * (1.0f / (float)HW);
    __nv_bfloat16 h, l;
    split_bf16(val, h, l);
    const size_t t = (size_t)bq * NC * NC + (size_t)j * NC + i;
    g_gTh[t] = h;
    g_gTl[t] = l;
}

// ---------------------------------------------------------------------------
// Kernel O: out[b,j,n] = sum_i av[i,n]*gd[i,j];  av = exp(V-mV)*sV
// k-chunked (16) double-buffered both operands. grid (HW/128, NB), 256 threads.
// smem: G 2buf x (h+l)[128][24] + F 2buf x (h+l)[16][136]  (~41 KB)
// ---------------------------------------------------------------------------
#define OUT_SMEM (2*2*128*LDW*2 + 2*2*16*LDA*2)

__global__ __launch_bounds__(256, 2) void out_wmma(float* __restrict__ out)
{
    extern __shared__ char smraw[];
    __nv_bfloat16* sG = (__nv_bfloat16*)smraw;          // 2 bufs x (h:128*LDW | l:128*LDW)
    __nv_bfloat16* sF = sG + 4*128*LDW;                 // 2 bufs x (h:16*LDA | l:16*LDA)

    const int tid = threadIdx.x, w = tid >> 5;
    const int b = blockIdx.y, n0 = blockIdx.x * 128;
    const int wm = w & 3, wn = w >> 2;

    // G chunk thread mapping
    const int gj = tid >> 1, gi8 = (tid & 1) * 8;
    const __nv_bfloat16* gTh = g_gTh + (size_t)b * NC * NC + gj * NC + gi8;
    const __nv_bfloat16* gTl = g_gTl + (size_t)b * NC * NC + gj * NC + gi8;
    // F chunk thread mapping
    const int fi = tid >> 4, fn8 = (tid & 15) * 8;

    auto load_F = [&](int kt, float* vbuf, float& mv, float& sv) {
        const int row = kt * 16 + fi;
        mv = g_mV[b * NC + row];
        sv = g_sV[b * NC + row];
        const float* Vp = g_V + ((size_t)b * NC + row) * HW + n0 + fn8;
        *(float4*)(vbuf)     = *(const float4*)(Vp);
        *(float4*)(vbuf + 4) = *(const float4*)(Vp + 4);
    };
    auto store_F = [&](int buf, const float* vbuf, float mv, float sv) {
        __nv_bfloat16* fh = sF + buf*2*16*LDA + fi*LDA + fn8;
        __nv_bfloat16* fl = fh + 16*LDA;
        #pragma unroll
        for (int k = 0; k < 8; k += 2) {
            float f0 = __expf(vbuf[k]   - mv) * sv;
            float f1 = __expf(vbuf[k+1] - mv) * sv;
            __nv_bfloat16 h0, l0, h1, l1;
            split_bf16(f0, h0, l0);
            split_bf16(f1, h1, l1);
            *(__nv_bfloat162*)&fh[k] = __halves2bfloat162(h0, h1);
            *(__nv_bfloat162*)&fl[k] = __halves2bfloat162(l0, l1);
        }
    };

    // chunk 0 -> buf 0
    {
        uint4 h = *(const uint4*)gTh;
        uint4 l = *(const uint4*)gTl;
        float vb[8], mv, sv;
        load_F(0, vb, mv, sv);
        *(uint4*)&sG[0*2*128*LDW + gj*LDW + gi8]           = h;
        *(uint4*)&sG[0*2*128*LDW + 128*LDW + gj*LDW + gi8] = l;
        store_F(0, vb, mv, sv);
    }
    __syncthreads();

    wmma::fragment<wmma::accumulator, 16, 16, 16, float> acc[2][4];
    #pragma unroll
    for (int mt = 0; mt < 2; mt++)
        #pragma unroll
        for (int nt = 0; nt < 4; nt++)
            wmma::fill_fragment(acc[mt][nt], 0.0f);

    #pragma unroll
    for (int kt = 0; kt < 8; kt++) {
        const int cur = kt & 1;
        __nv_bfloat16* bGh = sG + cur*2*128*LDW;
        __nv_bfloat16* bGl = bGh + 128*LDW;
        __nv_bfloat16* bFh = sF + cur*2*16*LDA;
        __nv_bfloat16* bFl = bFh + 16*LDA;

        uint4 ph, pl;
        float vb[8], mv, sv;
        if (kt < 7) {
            ph = *(const uint4*)(gTh + (kt+1)*16);
            pl = *(const uint4*)(gTl + (kt+1)*16);
            load_F(kt+1, vb, mv, sv);
        }

        wmma::fragment<wmma::matrix_a, 16, 16, 16, __nv_bfloat16, wmma::row_major> ah[2], al[2];
        #pragma unroll
        for (int mt = 0; mt < 2; mt++) {
            const int j0 = wm*32 + mt*16;
            wmma::load_matrix_sync(ah[mt], &bGh[j0*LDW], LDW);
            wmma::load_matrix_sync(al[mt], &bGl[j0*LDW], LDW);
        }
        #pragma unroll
        for (int nt = 0; nt < 4; nt++) {
            wmma::fragment<wmma::matrix_b, 16, 16, 16, __nv_bfloat16, wmma::row_major> bh, bl;
            const int c0 = wn*64 + nt*16;
            wmma::load_matrix_sync(bh, &bFh[c0], LDA);
            wmma::load_matrix_sync(bl, &bFl[c0], LDA);
            #pragma unroll
            for (int mt = 0; mt < 2; mt++) {
                wmma::mma_sync(acc[mt][nt], ah[mt], bh, acc[mt][nt]);
                wmma::mma_sync(acc[mt][nt], ah[mt], bl, acc[mt][nt]);
                wmma::mma_sync(acc[mt][nt], al[mt], bh, acc[mt][nt]);
            }
        }

        if (kt < 7) {
            const int nb = cur ^ 1;
            *(uint4*)&sG[nb*2*128*LDW + gj*LDW + gi8]           = ph;
            *(uint4*)&sG[nb*2*128*LDW + 128*LDW + gj*LDW + gi8] = pl;
            store_F(nb, vb, mv, sv);
        }
        __syncthreads();
    }

    #pragma unroll
    for (int mt = 0; mt < 2; mt++)
        #pragma unroll
        for (int nt = 0; nt < 4; nt++) {
            float* gp = out + ((size_t)b * NC + wm*32 + mt*16) * HW + n0 + wn*64 + nt*16;
            wmma::store_matrix_sync(gp, acc[mt][nt], HW, wmma::mem_row_major);
        }
}

// ---------------------------------------------------------------------------
extern "C" void kernel_launch(void* const* d_in, const int* in_sizes, int n_in,
                              void* d_out, int out_size)
{
    const float* x  = (const float*)d_in[0];
    const float* wA = (const float*)d_in[1];
    const float* bA = (const float*)d_in[2];
    const float* wB = (const float*)d_in[3];
    const float* bB = (const float*)d_in[4];  // unused: softmax shift-invariant
    const float* wV = (const float*)d_in[5];
    const float* bV = (const float*)d_in[6];  // unused: softmax shift-invariant
    (void)bB; (void)bV;
    float* out = (float*)d_out;

    cudaFuncSetAttribute(proj_wmma, cudaFuncAttributeMaxDynamicSharedMemorySize, PROJ_SMEM);
    cudaFuncSetAttribute(gd_wmma,   cudaFuncAttributeMaxDynamicSharedMemorySize, GD_SMEM);
    cudaFuncSetAttribute(out_wmma,  cudaFuncAttributeMaxDynamicSharedMemorySize, OUT_SMEM);

    wconv_kernel <<<3, 256>>>(wA, wB, wV);
    proj_wmma    <<<dim3(HW/128, NB), 256, PROJ_SMEM>>>(x);
    stats_kernel <<<dim3(NROW, 2), 256>>>();
    gd_wmma      <<<dim3(KSPLIT, NB), 256, GD_SMEM>>>();
    reduce_kernel<<<(NB*NC*NC)/256, 256>>>(bA);
    out_wmma     <<<dim3(HW/128, NB), 256, OUT_SMEM>>>(out);
}

// round 5
// speedup vs baseline: 1.5867x; 1.0285x over previous
#include <cuda_runtime.h>
#include <cuda_bf16.h>
#include <mma.h>
#include <cstdint>

using namespace nvcuda;

#define NB 32
#define NC 128
#define HW 4096
#define NROW (NB*NC)
#define KSPLIT 16

#define LDA 136   // padded ld for 128-wide bf16 tiles (272B rows -> conflict-free)
#define LDE 72    // padded ld for 64-wide bf16 tiles
#define LDW 24    // padded ld for 16-wide bf16 k-chunks

// Scratch (device globals: allocation-free kernel_launch)
__device__ __nv_bfloat16 g_Ah[NB*NC*HW], g_Al[NB*NC*HW];   // A (no bias)
__device__ __nv_bfloat16 g_Eh[NB*NC*HW], g_El[NB*NC*HW];   // exp(B)
__device__ __nv_bfloat16 g_Fh[NB*NC*HW], g_Fl[NB*NC*HW];   // exp(V)
__device__ float g_gdp[KSPLIT*NB*NC*NC];
__device__ __nv_bfloat16 g_gTh[NB*NC*NC];   // gd'^T [b][j][i] hi
__device__ __nv_bfloat16 g_gTl[NB*NC*NC];   // lo
__device__ float g_zBp[32*NROW], g_zVp[32*NROW];  // per-nblock partial sums of exp
__device__ float g_scl[NROW], g_bscl[NROW];       // 1/(zB*HW*zV), 1/(HW*zV)
__device__ __nv_bfloat16 g_wh[3*NC*NC], g_wl[3*NC*NC];

__device__ __forceinline__ void split_bf16(float f, __nv_bfloat16& h, __nv_bfloat16& l) {
    h = __float2bfloat16(f);
    l = __float2bfloat16(f - __bfloat162float(h));
}

// ---------------------------------------------------------------------------
// Kernel W: weights -> bf16 hi/lo
// ---------------------------------------------------------------------------
__global__ __launch_bounds__(256) void wconv_kernel(
    const float* __restrict__ wA, const float* __restrict__ wB, const float* __restrict__ wV)
{
    const float* ws[3] = {wA, wB, wV};
    const int m = blockIdx.x;
    const float* w = ws[m];
    for (int idx = threadIdx.x; idx < NC*NC; idx += 256) {
        __nv_bfloat16 h, l;
        split_bf16(w[idx], h, l);
        g_wh[m*NC*NC + idx] = h;
        g_wl[m*NC*NC + idx] = l;
    }
}

// ---------------------------------------------------------------------------
// Kernel P: projections, k-chunked double-buffered W; epilogue computes
//   m=0: A -> bf16 pair;  m=1: E=exp(B) -> pair + row partial sums;
//   m=2: F=exp(V) -> pair + row partial sums.  (bB/bV softmax-invariant)
// grid (HW/128, NB), 256 threads.
// ---------------------------------------------------------------------------
#define PROJ_SMEM (2*128*LDA*2 + 2*2*128*LDW*2 + 8*16*20*4 + 2*128*4*4)

__global__ __launch_bounds__(256, 2) void proj_wmma(const float* __restrict__ x)
{
    extern __shared__ char smraw[];
    __nv_bfloat16* sXh = (__nv_bfloat16*)smraw;
    __nv_bfloat16* sXl = sXh + 128*LDA;
    __nv_bfloat16* sW  = sXl + 128*LDA;               // 2 bufs x (h:128*LDW | l:128*LDW)
    float* stage = (float*)(sW + 4*128*LDW);          // 8 warps x 16x20
    float* zsmB  = stage + 8*16*20;                   // [128][4]
    float* zsmV  = zsmB + 128*4;

    const int tid = threadIdx.x, w = tid >> 5, lane = tid & 31;
    const int b = blockIdx.y, n0 = blockIdx.x * 128;
    const int wm = w & 3, wn = w >> 2;
    const int o_ = tid >> 1, k8_ = (tid & 1) * 8;

    // x tile -> bf16 hi/lo in smem [c][n]
    {
        const int c = tid >> 1, nh = (tid & 1) * 64;
        const float* xp = x + ((size_t)b * NC + c) * HW + n0 + nh;
        #pragma unroll 8
        for (int k = 0; k < 64; k += 2) {
            __nv_bfloat16 h0, l0, h1, l1;
            split_bf16(xp[k],   h0, l0);
            split_bf16(xp[k+1], h1, l1);
            *(__nv_bfloat162*)&sXh[c*LDA + nh + k] = __halves2bfloat162(h0, h1);
            *(__nv_bfloat162*)&sXl[c*LDA + nh + k] = __halves2bfloat162(l0, l1);
        }
    }

    for (int m = 0; m < 3; m++) {
        const __nv_bfloat16* wh = g_wh + m*NC*NC + o_*NC + k8_;
        const __nv_bfloat16* wl = g_wl + m*NC*NC + o_*NC + k8_;

        // chunk 0 -> buf 0
        {
            uint4 h = *(const uint4*)wh;
            uint4 l = *(const uint4*)wl;
            __syncthreads();
            *(uint4*)&sW[0*2*128*LDW + o_*LDW + k8_]           = h;
            *(uint4*)&sW[0*2*128*LDW + 128*LDW + o_*LDW + k8_] = l;
        }
        __syncthreads();

        wmma::fragment<wmma::accumulator, 16, 16, 16, float> acc[2][4];
        #pragma unroll
        for (int mt = 0; mt < 2; mt++)
            #pragma unroll
            for (int nt = 0; nt < 4; nt++)
                wmma::fill_fragment(acc[mt][nt], 0.0f);

        #pragma unroll
        for (int kt = 0; kt < 8; kt++) {
            const int cur = kt & 1;
            __nv_bfloat16* bWh = sW + cur*2*128*LDW;
            __nv_bfloat16* bWl = bWh + 128*LDW;

            uint4 ph, pl;
            if (kt < 7) {
                ph = *(const uint4*)(wh + (kt+1)*16);
                pl = *(const uint4*)(wl + (kt+1)*16);
            }

            wmma::fragment<wmma::matrix_a, 16, 16, 16, __nv_bfloat16, wmma::row_major> ah[2], al[2];
            #pragma unroll
            for (int mt = 0; mt < 2; mt++) {
                const int o0 = wm*32 + mt*16;
                wmma::load_matrix_sync(ah[mt], &bWh[o0*LDW], LDW);
                wmma::load_matrix_sync(al[mt], &bWl[o0*LDW], LDW);
            }
            #pragma unroll
            for (int nt = 0; nt < 4; nt++) {
                wmma::fragment<wmma::matrix_b, 16, 16, 16, __nv_bfloat16, wmma::row_major> bh, bl;
                const int c0 = wn*64 + nt*16;
                wmma::load_matrix_sync(bh, &sXh[kt*16*LDA + c0], LDA);
                wmma::load_matrix_sync(bl, &sXl[kt*16*LDA + c0], LDA);
                #pragma unroll
                for (int mt = 0; mt < 2; mt++) {
                    wmma::mma_sync(acc[mt][nt], ah[mt], bh, acc[mt][nt]);
                    wmma::mma_sync(acc[mt][nt], ah[mt], bl, acc[mt][nt]);
                    wmma::mma_sync(acc[mt][nt], al[mt], bh, acc[mt][nt]);
                }
            }

            if (kt < 7) {
                __nv_bfloat16* nWh = sW + (cur^1)*2*128*LDW;
                *(uint4*)&nWh[o_*LDW + k8_]           = ph;
                *(uint4*)&nWh[128*LDW + o_*LDW + k8_] = pl;
            }
            __syncthreads();
        }

        // Epilogue: stage each tile, convert, store; m>=1 also exp + row sums
        float* st = stage + w * 16 * 20;
        float rs0 = 0.f, rs1 = 0.f;
        __nv_bfloat16* dh = (m == 0) ? g_Ah : (m == 1) ? g_Eh : g_Fh;
        __nv_bfloat16* dl = (m == 0) ? g_Al : (m == 1) ? g_El : g_Fl;
        #pragma unroll
        for (int mt = 0; mt < 2; mt++)
            #pragma unroll
            for (int nt = 0; nt < 4; nt++) {
                wmma::store_matrix_sync(st, acc[mt][nt], 20, wmma::mem_row_major);
                __syncwarp();
                const int r = lane & 15, c8 = (lane >> 4) * 8;
                const int o = wm*32 + mt*16 + r;
                const int nn = n0 + wn*64 + nt*16 + c8;
                const float* sp = st + r*20 + c8;
                const size_t gb = ((size_t)b * NC + o) * HW + nn;
                float v[8];
                #pragma unroll
                for (int k = 0; k < 8; k++) v[k] = sp[k];
                if (m > 0) {
                    float lsum = 0.f;
                    #pragma unroll
                    for (int k = 0; k < 8; k++) { v[k] = __expf(v[k]); lsum += v[k]; }
                    if (mt == 0) rs0 += lsum; else rs1 += lsum;
                }
                #pragma unroll
                for (int k = 0; k < 8; k += 2) {
                    __nv_bfloat16 h0, l0, h1, l1;
                    split_bf16(v[k],   h0, l0);
                    split_bf16(v[k+1], h1, l1);
                    *(__nv_bfloat162*)&dh[gb + k] = __halves2bfloat162(h0, h1);
                    *(__nv_bfloat162*)&dl[gb + k] = __halves2bfloat162(l0, l1);
                }
                __syncwarp();
            }
        if (m > 0) {
            float* zz = (m == 1) ? zsmB : zsmV;
            const int idx = wn*2 + (lane >> 4), r = lane & 15;
            zz[(wm*32 + r)*4 + idx]      = rs0;
            zz[(wm*32 + 16 + r)*4 + idx] = rs1;
        }
    }

    __syncthreads();
    if (tid < 128) {
        float zb = zsmB[tid*4] + zsmB[tid*4+1] + zsmB[tid*4+2] + zsmB[tid*4+3];
        float zv = zsmV[tid*4] + zsmV[tid*4+1] + zsmV[tid*4+2] + zsmV[tid*4+3];
        g_zBp[blockIdx.x*NROW + b*NC + tid] = zb;
        g_zVp[blockIdx.x*NROW + b*NC + tid] = zv;
    }
}

// ---------------------------------------------------------------------------
// Kernel Z: finalize per-row scales (deterministic sum of 32 partials)
// ---------------------------------------------------------------------------
__global__ __launch_bounds__(256) void zfin_kernel()
{
    const int row = blockIdx.x * 256 + threadIdx.x;   // < NROW
    float zb = 0.f, zv = 0.f;
    #pragma unroll
    for (int nb = 0; nb < 32; nb++) {
        zb += g_zBp[nb*NROW + row];
        zv += g_zVp[nb*NROW + row];
    }
    g_scl[row]  = 1.0f / (zb * (float)HW * zv);
    g_bscl[row] = 1.0f / ((float)HW * zv);
}

// ---------------------------------------------------------------------------
// Kernel G: gdp[s][b][i][j] = sum_{n in 256-chunk} E[i,n]*A[j,n]
// block tile 128i x 64j (jhalf via blockIdx.z), warp tile 32x32, 256 thr, 3 blk/SM
// ---------------------------------------------------------------------------
#define GD_SMEM ((2*128*LDE + 2*64*LDE)*2)

__global__ __launch_bounds__(256, 3) void gd_wmma()
{
    extern __shared__ char smraw[];
    __nv_bfloat16* sEh = (__nv_bfloat16*)smraw;
    __nv_bfloat16* sEl = sEh + 128*LDE;
    __nv_bfloat16* sAh = sEl + 128*LDE;
    __nv_bfloat16* sAl = sAh + 64*LDE;

    const int tid = threadIdx.x, w = tid >> 5;
    const int s = blockIdx.x, b = blockIdx.y, jh = blockIdx.z;
    const int kbase = s * 256;
    const int wi = w & 3, wj = w >> 2;

    wmma::fragment<wmma::accumulator, 16, 16, 16, float> acc[2][2];
    #pragma unroll
    for (int mt = 0; mt < 2; mt++)
        #pragma unroll
        for (int nt = 0; nt < 2; nt++)
            wmma::fill_fragment(acc[mt][nt], 0.0f);

    // staging thread mappings
    const int er = tid >> 1, eh32 = (tid & 1) * 32;
    const int ar = tid >> 2, ah16 = (tid & 3) * 16;

    for (int kt4 = 0; kt4 < 4; kt4++) {
        const int kk0 = kbase + kt4 * 64;
        __syncthreads();
        {
            const uint4* peh = (const uint4*)(g_Eh + ((size_t)(b*NC + er))*HW + kk0 + eh32);
            const uint4* pel = (const uint4*)(g_El + ((size_t)(b*NC + er))*HW + kk0 + eh32);
            uint4* deh = (uint4*)&sEh[er*LDE + eh32];
            uint4* del = (uint4*)&sEl[er*LDE + eh32];
            #pragma unroll
            for (int q = 0; q < 4; q++) { deh[q] = peh[q]; del[q] = pel[q]; }

            const uint4* pah = (const uint4*)(g_Ah + ((size_t)(b*NC + jh*64 + ar))*HW + kk0 + ah16);
            const uint4* pal = (const uint4*)(g_Al + ((size_t)(b*NC + jh*64 + ar))*HW + kk0 + ah16);
            uint4* dah = (uint4*)&sAh[ar*LDE + ah16];
            uint4* dal = (uint4*)&sAl[ar*LDE + ah16];
            #pragma unroll
            for (int q = 0; q < 2; q++) { dah[q] = pah[q]; dal[q] = pal[q]; }
        }
        __syncthreads();

        #pragma unroll
        for (int kk = 0; kk < 4; kk++) {
            wmma::fragment<wmma::matrix_a, 16, 16, 16, __nv_bfloat16, wmma::row_major> ah[2], al[2];
            #pragma unroll
            for (int mt = 0; mt < 2; mt++) {
                const int i0 = wi*32 + mt*16;
                wmma::load_matrix_sync(ah[mt], &sEh[i0*LDE + kk*16], LDE);
                wmma::load_matrix_sync(al[mt], &sEl[i0*LDE + kk*16], LDE);
            }
            #pragma unroll
            for (int nt = 0; nt < 2; nt++) {
                wmma::fragment<wmma::matrix_b, 16, 16, 16, __nv_bfloat16, wmma::col_major> bh, bl;
                const int j0 = wj*32 + nt*16;
                wmma::load_matrix_sync(bh, &sAh[j0*LDE + kk*16], LDE);
                wmma::load_matrix_sync(bl, &sAl[j0*LDE + kk*16], LDE);
                #pragma unroll
                for (int mt = 0; mt < 2; mt++) {
                    wmma::mma_sync(acc[mt][nt], ah[mt], bh, acc[mt][nt]);
                    wmma::mma_sync(acc[mt][nt], ah[mt], bl, acc[mt][nt]);
                    wmma::mma_sync(acc[mt][nt], al[mt], bh, acc[mt][nt]);
                }
            }
        }
    }

    float* gp = g_gdp + ((size_t)s * NB + b) * NC * NC;
    #pragma unroll
    for (int mt = 0; mt < 2; mt++)
        #pragma unroll
        for (int nt = 0; nt < 2; nt++)
            wmma::store_matrix_sync(gp + (wi*32 + mt*16) * NC + jh*64 + wj*32 + nt*16,
                                    acc[mt][nt], NC, wmma::mem_row_major);
}

// ---------------------------------------------------------------------------
// Kernel R: gd' = (sum_s gdp)*scl[i] + bA[j]*bscl[i]; write gT' bf16 pair [b][j][i]
// ---------------------------------------------------------------------------
__global__ __launch_bounds__(256) void reduce_kernel(const float* __restrict__ bA)
{
    const int idx = blockIdx.x * 256 + threadIdx.x;   // b*16384 + i*128 + j
    const int bq = idx >> 14, i = (idx >> 7) & 127, j = idx & 127;
    float sum = 0.f;
    #pragma unroll
    for (int s = 0; s < KSPLIT; s++)
        sum += g_gdp[(size_t)s * (NB*NC*NC) + idx];
    const int irow = bq * NC + i;
    const float val = sum * g_scl[irow] + bA[j] * g_bscl[irow];
    __nv_bfloat16 h, l;
    split_bf16(val, h, l);
    const size_t t = (size_t)bq * NC * NC + (size_t)j * NC + i;
    g_gTh[t] = h;
    g_gTl[t] = l;
}

// ---------------------------------------------------------------------------
// Kernel O: out[b,j,n] = sum_i F[i,n]*gd'[i,j]  (pure bf16 GEMM, K=128)
// k-chunked (16) double-buffered. grid (HW/128, NB), 256 threads.
// ---------------------------------------------------------------------------
#define OUT_SMEM (2*2*128*LDW*2 + 2*2*16*LDA*2)

__global__ __launch_bounds__(256, 2) void out_wmma(float* __restrict__ out)
{
    extern __shared__ char smraw[];
    __nv_bfloat16* sG = (__nv_bfloat16*)smraw;          // 2 bufs x (h:128*LDW | l:128*LDW)
    __nv_bfloat16* sF = sG + 4*128*LDW;                 // 2 bufs x (h:16*LDA | l:16*LDA)

    const int tid = threadIdx.x, w = tid >> 5;
    const int b = blockIdx.y, n0 = blockIdx.x * 128;
    const int wm = w & 3, wn = w >> 2;

    const int gj = tid >> 1, gi8 = (tid & 1) * 8;
    const __nv_bfloat16* gTh = g_gTh + (size_t)b * NC * NC + gj * NC + gi8;
    const __nv_bfloat16* gTl = g_gTl + (size_t)b * NC * NC + gj * NC + gi8;
    const int fi = tid >> 4, fn8 = (tid & 15) * 8;

    // chunk 0 -> buf 0
    {
        uint4 h  = *(const uint4*)gTh;
        uint4 l  = *(const uint4*)gTl;
        uint4 fh = *(const uint4*)(g_Fh + ((size_t)(b*NC + fi))*HW + n0 + fn8);
        uint4 fl = *(const uint4*)(g_Fl + ((size_t)(b*NC + fi))*HW + n0 + fn8);
        *(uint4*)&sG[0*2*128*LDW + gj*LDW + gi8]           = h;
        *(uint4*)&sG[0*2*128*LDW + 128*LDW + gj*LDW + gi8] = l;
        *(uint4*)&sF[0*2*16*LDA + fi*LDA + fn8]            = fh;
        *(uint4*)&sF[0*2*16*LDA + 16*LDA + fi*LDA + fn8]   = fl;
    }
    __syncthreads();

    wmma::fragment<wmma::accumulator, 16, 16, 16, float> acc[2][4];
    #pragma unroll
    for (int mt = 0; mt < 2; mt++)
        #pragma unroll
        for (int nt = 0; nt < 4; nt++)
            wmma::fill_fragment(acc[mt][nt], 0.0f);

    #pragma unroll
    for (int kt = 0; kt < 8; kt++) {
        const int cur = kt & 1;
        __nv_bfloat16* bGh = sG + cur*2*128*LDW;
        __nv_bfloat16* bGl = bGh + 128*LDW;
        __nv_bfloat16* bFh = sF + cur*2*16*LDA;
        __nv_bfloat16* bFl = bFh + 16*LDA;

        uint4 ph, pl, fh, fl;
        if (kt < 7) {
            ph = *(const uint4*)(gTh + (kt+1)*16);
            pl = *(const uint4*)(gTl + (kt+1)*16);
            fh = *(const uint4*)(g_Fh + ((size_t)(b*NC + (kt+1)*16 + fi))*HW + n0 + fn8);
            fl = *(const uint4*)(g_Fl + ((size_t)(b*NC + (kt+1)*16 + fi))*HW + n0 + fn8);
        }

        wmma::fragment<wmma::matrix_a, 16, 16, 16, __nv_bfloat16, wmma::row_major> ah[2], al[2];
        #pragma unroll
        for (int mt = 0; mt < 2; mt++) {
            const int j0 = wm*32 + mt*16;
            wmma::load_matrix_sync(ah[mt], &bGh[j0*LDW], LDW);
            wmma::load_matrix_sync(al[mt], &bGl[j0*LDW], LDW);
        }
        #pragma unroll
        for (int nt = 0; nt < 4; nt++) {
            wmma::fragment<wmma::matrix_b, 16, 16, 16, __nv_bfloat16, wmma::row_major> bh, bl;
            const int c0 = wn*64 + nt*16;
            wmma::load_matrix_sync(bh, &bFh[c0], LDA);
            wmma::load_matrix_sync(bl, &bFl[c0], LDA);
            #pragma unroll
            for (int mt = 0; mt < 2; mt++) {
                wmma::mma_sync(acc[mt][nt], ah[mt], bh, acc[mt][nt]);
                wmma::mma_sync(acc[mt][nt], ah[mt], bl, acc[mt][nt]);
                wmma::mma_sync(acc[mt][nt], al[mt], bh, acc[mt][nt]);
            }
        }

        if (kt < 7) {
            const int nb = cur ^ 1;
            *(uint4*)&sG[nb*2*128*LDW + gj*LDW + gi8]           = ph;
            *(uint4*)&sG[nb*2*128*LDW + 128*LDW + gj*LDW + gi8] = pl;
            *(uint4*)&sF[nb*2*16*LDA + fi*LDA + fn8]            = fh;
            *(uint4*)&sF[nb*2*16*LDA + 16*LDA + fi*LDA + fn8]   = fl;
        }
        __syncthreads();
    }

    #pragma unroll
    for (int mt = 0; mt < 2; mt++)
        #pragma unroll
        for (int nt = 0; nt < 4; nt++) {
            float* gp = out + ((size_t)b * NC + wm*32 + mt*16) * HW + n0 + wn*64 + nt*16;
            wmma::store_matrix_sync(gp, acc[mt][nt], HW, wmma::mem_row_major);
        }
}

// ---------------------------------------------------------------------------
extern "C" void kernel_launch(void* const* d_in, const int* in_sizes, int n_in,
                              void* d_out, int out_size)
{
    const float* x  = (const float*)d_in[0];
    const float* wA = (const float*)d_in[1];
    const float* bA = (const float*)d_in[2];
    const float* wB = (const float*)d_in[3];
    const float* bB = (const float*)d_in[4];  // unused: softmax shift-invariant
    const float* wV = (const float*)d_in[5];
    const float* bV = (const float*)d_in[6];  // unused: softmax shift-invariant
    (void)bB; (void)bV;
    float* out = (float*)d_out;

    cudaFuncSetAttribute(proj_wmma, cudaFuncAttributeMaxDynamicSharedMemorySize, PROJ_SMEM);
    cudaFuncSetAttribute(gd_wmma,   cudaFuncAttributeMaxDynamicSharedMemorySize, GD_SMEM);
    cudaFuncSetAttribute(out_wmma,  cudaFuncAttributeMaxDynamicSharedMemorySize, OUT_SMEM);

    wconv_kernel <<<3, 256>>>(wA, wB, wV);
    proj_wmma    <<<dim3(HW/128, NB), 256, PROJ_SMEM>>>(x);
    zfin_kernel  <<<NROW/256, 256>>>();
    gd_wmma      <<<dim3(KSPLIT, NB, 2), 256, GD_SMEM>>>();
    reduce_kernel<<<(NB*NC*NC)/256, 256>>>(bA);
    out_wmma     <<<dim3(HW/128, NB), 256, OUT_SMEM>>>(out);
}